// round 3
// baseline (speedup 1.0000x reference)
#include <cuda_runtime.h>
#include <cuda_bf16.h>
#include <cstdint>

// x:   [B=64, C=12, 224, 224] fp32
// w:   [C=12, E=768] fp32
// out: [B=64, P=196, E=768] fp32
//
// out[b, p, e] = (sum of 16x16 patch p of channel c of x) dot w[c, e]
//
// CTA = (batch, patch-row). Loads the full 12-channel x strip (16 rows x 224
// cols) with 16 independent float4 loads per thread, reduces to
// pooled[12][14] in smem, then emits the contiguous 14x768 output slab.

#define IMG   224
#define NP    14
#define C_IN  12
#define EMBED 768
#define NQ    56          // float4 columns per image row (224/4)
#define NTHREADS (C_IN * NQ)   // 672 = 21 warps

__global__ __launch_bounds__(NTHREADS, 2) void patch_strip_embed_kernel(
    const float* __restrict__ x,
    const float* __restrict__ w,
    float* __restrict__ out)
{
    const int pi  = blockIdx.x;          // patch row 0..13
    const int b   = blockIdx.y;          // 0..63
    const int tid = threadIdx.x;
    const int c   = tid / NQ;            // channel 0..11
    const int q   = tid % NQ;            // float4 column 0..55

    __shared__ float pooled[C_IN][NP];

    // ---- Phase 1: 16 independent column loads, one scalar accumulator pair ----
    const float4* base = reinterpret_cast<const float4*>(
        x + ((size_t)(b * C_IN + c) * IMG + (size_t)pi * 16) * IMG) + q;

    float s0 = 0.0f, s1 = 0.0f;
    #pragma unroll
    for (int r = 0; r < 16; r += 2) {
        const float4 v0 = base[(size_t)r * NQ];
        const float4 v1 = base[(size_t)(r + 1) * NQ];
        s0 += (v0.x + v0.y) + (v0.z + v0.w);
        s1 += (v1.x + v1.y) + (v1.z + v1.w);
    }
    float s = s0 + s1;

    // 4 consecutive lanes = 4 float4 columns of one patch (56 % 4 == 0, so a
    // group of 4 never straddles a channel or warp boundary).
    s += __shfl_xor_sync(0xffffffffu, s, 1);
    s += __shfl_xor_sync(0xffffffffu, s, 2);
    if ((q & 3) == 0)
        pooled[c][q >> 2] = s;
    __syncthreads();

    // ---- Phase 2: C->E contraction; 4 float4 outputs per thread ----
    float* o = out + ((size_t)b * (NP * NP) + (size_t)pi * NP) * EMBED;

    #pragma unroll
    for (int k = 0; k < 4; ++k) {
        const int i  = tid + k * NTHREADS;   // 0..2687 float4 slots
        const int p  = i / (EMBED / 4);      // local patch 0..13
        const int e0 = (i % (EMBED / 4)) * 4;

        float4 acc = make_float4(0.f, 0.f, 0.f, 0.f);
        #pragma unroll
        for (int cc = 0; cc < C_IN; ++cc) {
            const float pc = pooled[cc][p];
            const float4 wv = *reinterpret_cast<const float4*>(&w[cc * EMBED + e0]);
            acc.x = fmaf(pc, wv.x, acc.x);
            acc.y = fmaf(pc, wv.y, acc.y);
            acc.z = fmaf(pc, wv.z, acc.z);
            acc.w = fmaf(pc, wv.w, acc.w);
        }
        *reinterpret_cast<float4*>(o + (size_t)p * EMBED + e0) = acc;
    }
}

extern "C" void kernel_launch(void* const* d_in, const int* in_sizes, int n_in,
                              void* d_out, int out_size)
{
    const float* x = (const float*)d_in[0];
    const float* w = (const float*)d_in[1];
    float* out = (float*)d_out;

    dim3 grid(NP, 64);   // 896 CTAs
    patch_strip_embed_kernel<<<grid, NTHREADS>>>(x, w, out);
}